// round 1
// baseline (speedup 1.0000x reference)
#include <cuda_runtime.h>
#include <math.h>

#define BB 2
#define NN 2048
#define DM 512
#define NH 8
#define HD 64
#define TOPK 64
#define BH (BB*NH)       // 16
#define M_TOT (BB*NN)    // 4096
#define SCALEF 0.125f

// ---------------- scratch (static __device__ per allocation rules) ----------
__device__ float g_Qh[BH*NN*HD];            // [bh][n][d]  8MB
__device__ float g_Kh[BH*NN*HD];
__device__ float g_Vh[BH*NN*HD];
__device__ float g_S[(size_t)BH*NN*NN];     // raw scores 256MB
__device__ float g_H[M_TOT*DM];             // merged-head attn output 8MB

// ---------------------------------------------------------------------------
// Generic fp32 GEMM with bias:  C[m][o] = sum_k X[m][k]*W[o][k] + bias[o]
// mode 0/1/2 : X from param, write head-split into g_Qh/g_Kh/g_Vh
// mode 3     : X = g_H, write plain row-major into out_param
// Tile 64x64, BK=16, 256 threads, 4x4 micro-tile, LDS.128 via transposed smem.
// ---------------------------------------------------------------------------
__global__ void gemm_bias(const float* __restrict__ Xp,
                          const float* __restrict__ W,
                          const float* __restrict__ bias,
                          float* __restrict__ out_param,
                          int mode)
{
    const float* X = (mode == 3) ? g_H : Xp;
    float* out = (mode == 0) ? g_Qh : (mode == 1) ? g_Kh : (mode == 2) ? g_Vh : out_param;

    __shared__ float AsT[16][68];   // [k][m], stride 68 keeps rows 16B aligned
    __shared__ float Bs [16][68];   // [k][o]

    const int m0 = blockIdx.y * 64;
    const int o0 = blockIdx.x * 64;
    const int tid = threadIdx.x;
    const int tx = tid & 15, ty = tid >> 4;
    const int lr  = tid >> 2;         // 0..63
    const int lc4 = (tid & 3) * 4;    // 0,4,8,12

    float acc[4][4];
#pragma unroll
    for (int i = 0; i < 4; i++)
#pragma unroll
        for (int j = 0; j < 4; j++) acc[i][j] = 0.f;

    for (int k0 = 0; k0 < DM; k0 += 16) {
        float4 av = *(const float4*)&X[(size_t)(m0 + lr) * DM + k0 + lc4];
        float4 bv = *(const float4*)&W[(size_t)(o0 + lr) * DM + k0 + lc4];
        AsT[lc4 + 0][lr] = av.x; AsT[lc4 + 1][lr] = av.y;
        AsT[lc4 + 2][lr] = av.z; AsT[lc4 + 3][lr] = av.w;
        Bs [lc4 + 0][lr] = bv.x; Bs [lc4 + 1][lr] = bv.y;
        Bs [lc4 + 2][lr] = bv.z; Bs [lc4 + 3][lr] = bv.w;
        __syncthreads();
#pragma unroll
        for (int kk = 0; kk < 16; kk++) {
            float4 a = *(const float4*)&AsT[kk][ty * 4];
            float4 b = *(const float4*)&Bs [kk][tx * 4];
            acc[0][0] += a.x * b.x; acc[0][1] += a.x * b.y; acc[0][2] += a.x * b.z; acc[0][3] += a.x * b.w;
            acc[1][0] += a.y * b.x; acc[1][1] += a.y * b.y; acc[1][2] += a.y * b.z; acc[1][3] += a.y * b.w;
            acc[2][0] += a.z * b.x; acc[2][1] += a.z * b.y; acc[2][2] += a.z * b.z; acc[2][3] += a.z * b.w;
            acc[3][0] += a.w * b.x; acc[3][1] += a.w * b.y; acc[3][2] += a.w * b.z; acc[3][3] += a.w * b.w;
        }
        __syncthreads();
    }

#pragma unroll
    for (int i = 0; i < 4; i++) {
        int m = m0 + ty * 4 + i;
#pragma unroll
        for (int j = 0; j < 4; j++) {
            int o = o0 + tx * 4 + j;
            float v = acc[i][j] + bias[o];
            if (mode < 3) {
                int b = m >> 11, n = m & (NN - 1);
                int h = o >> 6,  d = o & 63;
                out[(size_t)((b * NH + h) * NN + n) * HD + d] = v;
            } else {
                out[(size_t)m * DM + o] = v;
            }
        }
    }
}

// ---------------------------------------------------------------------------
// Scores: for each (b,h), S = Qh (2048x64) @ Kh^T * SCALE.  Full K-dim (=64)
// resident in smem; 64x64 output tiles, 4x4 micro-tile, LDS.128.
// grid (32, 32, 16), 256 threads.
// ---------------------------------------------------------------------------
__global__ void scores_kernel()
{
    const int bh = blockIdx.z;
    const int k0 = blockIdx.x * 64;
    const int q0 = blockIdx.y * 64;

    __shared__ float QsT[64][68];   // [d][r]
    __shared__ float KsT[64][68];   // [d][c]

    const int tid = threadIdx.x;
    for (int idx = tid; idx < 4096; idx += 256) {
        int r = idx >> 6, d = idx & 63;
        QsT[d][r] = g_Qh[(size_t)(bh * NN + q0 + r) * HD + d];
        KsT[d][r] = g_Kh[(size_t)(bh * NN + k0 + r) * HD + d];
    }
    __syncthreads();

    const int tx = tid & 15, ty = tid >> 4;
    float acc[4][4];
#pragma unroll
    for (int i = 0; i < 4; i++)
#pragma unroll
        for (int j = 0; j < 4; j++) acc[i][j] = 0.f;

#pragma unroll 8
    for (int d = 0; d < 64; d++) {
        float4 a = *(const float4*)&QsT[d][ty * 4];
        float4 b = *(const float4*)&KsT[d][tx * 4];
        acc[0][0] += a.x * b.x; acc[0][1] += a.x * b.y; acc[0][2] += a.x * b.z; acc[0][3] += a.x * b.w;
        acc[1][0] += a.y * b.x; acc[1][1] += a.y * b.y; acc[1][2] += a.y * b.z; acc[1][3] += a.y * b.w;
        acc[2][0] += a.z * b.x; acc[2][1] += a.z * b.y; acc[2][2] += a.z * b.z; acc[2][3] += a.z * b.w;
        acc[3][0] += a.w * b.x; acc[3][1] += a.w * b.y; acc[3][2] += a.w * b.z; acc[3][3] += a.w * b.w;
    }

#pragma unroll
    for (int i = 0; i < 4; i++) {
        size_t base = (size_t)(bh * NN + q0 + ty * 4 + i) * NN + k0 + tx * 4;
        float4 v = make_float4(acc[i][0] * SCALEF, acc[i][1] * SCALEF,
                               acc[i][2] * SCALEF, acc[i][3] * SCALEF);
        *(float4*)&g_S[base] = v;
    }
}

// ---------------------------------------------------------------------------
// Per-row: exact top-64 (MSB radix select on order-preserving uint keys),
// softmax over selected, write attn_weights row (incl. zeros), and
// out_head = sum_{sel} w * V.   grid 32768 blocks x 256 threads.
// ---------------------------------------------------------------------------
__global__ void topk_av(float* __restrict__ attn, int write_attn)
{
    const int row = blockIdx.x;           // bh*N + q
    const int bh  = row >> 11;
    const int q   = row & (NN - 1);
    const int tid = threadIdx.x;

    __shared__ int hist[256];
    __shared__ int scan[256];
    __shared__ float red[256];
    __shared__ int   sidx[128];
    __shared__ float sw[128];
    __shared__ unsigned sh_prefix;
    __shared__ int sh_kk;
    __shared__ int sh_cnt;

    // load 8 scores per thread (coalesced: element i = e*256 + tid)
    float sreg[8];
    unsigned keys[8];
#pragma unroll
    for (int e = 0; e < 8; e++) {
        float f = g_S[(size_t)row * NN + e * 256 + tid];
        sreg[e] = f;
        unsigned u = __float_as_uint(f);
        keys[e] = (u & 0x80000000u) ? ~u : (u | 0x80000000u);
    }

    // ---- radix select: kth(=64th) largest key, MSB-first, 4 passes ----
    unsigned prefix = 0;
    int kk = TOPK;
    for (int pass = 0; pass < 4; pass++) {
        hist[tid] = 0;
        __syncthreads();
        int shift = 24 - 8 * pass;
#pragma unroll
        for (int e = 0; e < 8; e++) {
            unsigned k = keys[e];
            unsigned hi = (k >> (31 - 8 * pass)) >> 1;   // top 8*pass bits (0 when pass==0)
            if (hi == prefix) atomicAdd(&hist[(k >> shift) & 255u], 1);
        }
        __syncthreads();
        scan[tid] = hist[tid];
        __syncthreads();
#pragma unroll
        for (int off = 1; off < 256; off <<= 1) {
            int v = (tid + off < 256) ? scan[tid + off] : 0;
            __syncthreads();
            scan[tid] += v;
            __syncthreads();
        }
        int above = scan[tid] - hist[tid];
        if (above < kk && scan[tid] >= kk && hist[tid] > 0) {
            sh_prefix = (prefix << 8) | (unsigned)tid;
            sh_kk = kk - above;
        }
        __syncthreads();
        prefix = sh_prefix;
        kk = sh_kk;
        __syncthreads();
    }
    const unsigned kth = prefix;   // exact 64th-largest key

    // ---- row max (== max of selected since max is always selected) ----
    float lmax = -3.4e38f;
#pragma unroll
    for (int e = 0; e < 8; e++) lmax = fmaxf(lmax, sreg[e]);
    red[tid] = lmax;
    __syncthreads();
#pragma unroll
    for (int off = 128; off > 0; off >>= 1) {
        if (tid < off) red[tid] = fmaxf(red[tid], red[tid + off]);
        __syncthreads();
    }
    const float rmax = red[0];
    __syncthreads();

    // ---- sum of exp over selected ----
    float lsum = 0.f;
#pragma unroll
    for (int e = 0; e < 8; e++)
        if (keys[e] >= kth) lsum += expf(sreg[e] - rmax);
    red[tid] = lsum;
    __syncthreads();
#pragma unroll
    for (int off = 128; off > 0; off >>= 1) {
        if (tid < off) red[tid] += red[tid + off];
        __syncthreads();
    }
    const float inv_z = 1.f / red[0];
    if (tid == 0) sh_cnt = 0;
    __syncthreads();

    // ---- weights: write attn row, gather selected (idx, w) ----
#pragma unroll
    for (int e = 0; e < 8; e++) {
        bool sel = (keys[e] >= kth);
        float w = sel ? expf(sreg[e] - rmax) * inv_z : 0.f;
        if (write_attn) attn[(size_t)row * NN + e * 256 + tid] = w;
        if (sel) {
            int p = atomicAdd(&sh_cnt, 1);
            if (p < 128) { sidx[p] = e * 256 + tid; sw[p] = w; }
        }
    }
    __syncthreads();
    int cnt = sh_cnt; if (cnt > 128) cnt = 128;

    // ---- AV: out[d] = sum_j w_j * V[bh][idx_j][d]  (only ~64 terms) ----
    const int d = tid & 63;
    const int part = tid >> 6;       // 0..3
    float acc = 0.f;
    for (int j = part; j < cnt; j += 4)
        acc += sw[j] * g_Vh[(size_t)(bh * NN + sidx[j]) * HD + d];
    red[tid] = acc;
    __syncthreads();
    if (tid < 64) {
        float o = red[tid] + red[64 + tid] + red[128 + tid] + red[192 + tid];
        int b = bh >> 3, h = bh & 7;
        g_H[(size_t)(b * NN + q) * DM + h * HD + tid] = o;
    }
}

// ---------------------------------------------------------------------------
extern "C" void kernel_launch(void* const* d_in, const int* in_sizes, int n_in,
                              void* d_out, int out_size)
{
    const float* q  = (const float*)d_in[0];
    const float* k  = (const float*)d_in[1];
    const float* v  = (const float*)d_in[2];
    const float* wq = (const float*)d_in[3];
    const float* bq = (const float*)d_in[4];
    const float* wk = (const float*)d_in[5];
    const float* bk = (const float*)d_in[6];
    const float* wv = (const float*)d_in[7];
    const float* bv = (const float*)d_in[8];
    const float* wo = (const float*)d_in[9];
    const float* bo = (const float*)d_in[10];

    float* out = (float*)d_out;
    const long long OUT_ELEMS  = (long long)M_TOT * DM;        // 2,097,152
    const long long ATTN_ELEMS = (long long)BH * NN * NN;      // 67,108,864

    int write_attn = 0, write_out = 1;
    float* attn_ptr = nullptr;
    if ((long long)out_size >= OUT_ELEMS + ATTN_ELEMS) {       // (out, attn_weights)
        write_attn = 1; attn_ptr = out + OUT_ELEMS;
    } else if ((long long)out_size == ATTN_ELEMS) {            // attn only (defensive)
        write_attn = 1; attn_ptr = out; write_out = 0;
    }                                                          // else: out only

    dim3 gemm_grid(DM / 64, M_TOT / 64);   // (8, 64)
    gemm_bias<<<gemm_grid, 256>>>(q, wq, bq, nullptr, 0);
    gemm_bias<<<gemm_grid, 256>>>(k, wk, bk, nullptr, 1);
    gemm_bias<<<gemm_grid, 256>>>(v, wv, bv, nullptr, 2);

    scores_kernel<<<dim3(NN / 64, NN / 64, BH), 256>>>();

    topk_av<<<BH * NN, 256>>>(attn_ptr, write_attn);

    if (write_out)
        gemm_bias<<<gemm_grid, 256>>>(nullptr, wo, bo, out, 3);
}

// round 2
// speedup vs baseline: 1.2362x; 1.2362x over previous
#include <cuda_runtime.h>
#include <math.h>

#define BB 2
#define NN 2048
#define DM 512
#define NH 8
#define HD 64
#define TOPK 64
#define BH (BB*NH)       // 16
#define M_TOT (BB*NN)    // 4096
#define SCALEF 0.125f

// ---------------- scratch (static __device__ per allocation rules) ----------
__device__ float g_Qh[BH*NN*HD];            // [bh][n][d]  (Q pre-scaled by 1/8)
__device__ float g_Kh[BH*NN*HD];
__device__ float g_Vh[BH*NN*HD];
__device__ float g_S[(size_t)BH*NN*NN];     // raw scores 256MB
__device__ float g_H[M_TOT*DM];             // merged-head attn output

// ---------------------------------------------------------------------------
// 128x128-tile fp32 GEMM, 8x8 micro-tile, BK=16, 256 threads.
// C[m][o] = sum_k X[m][k] * W[o][k] + bias[o]
// mode 0: fused QKV. blockIdx.x in [0,12): which = bx>>2 selects (X,W,bias),
//         o_local0 = (bx&3)*128. Output head-split into g_Qh/g_Kh/g_Vh,
//         Q additionally scaled by SCALEF.
// mode 1: out-projection. X = g_H, W = W0, bias = b0, plain row-major out.
// ---------------------------------------------------------------------------
__global__ __launch_bounds__(256)
void gemm128(const float* __restrict__ X0, const float* __restrict__ X1,
             const float* __restrict__ X2,
             const float* __restrict__ W0, const float* __restrict__ W1,
             const float* __restrict__ W2,
             const float* __restrict__ b0, const float* __restrict__ b1,
             const float* __restrict__ b2,
             float* __restrict__ outp, int mode)
{
    __shared__ float XsT[16][132];
    __shared__ float WsT[16][132];

    const int tid = threadIdx.x;
    const int tx = tid & 15, ty = tid >> 4;
    const int m0 = blockIdx.y * 128;

    int which = 0, o0 = 0;
    const float *X, *W, *bias;
    if (mode == 0) {
        which = blockIdx.x >> 2;
        o0 = (blockIdx.x & 3) * 128;
        X    = (which == 0) ? X0 : (which == 1) ? X1 : X2;
        W    = (which == 0) ? W0 : (which == 1) ? W1 : W2;
        bias = (which == 0) ? b0 : (which == 1) ? b1 : b2;
    } else {
        o0 = blockIdx.x * 128;
        X = g_H; W = W0; bias = b0;
    }

    float acc[8][8];
#pragma unroll
    for (int i = 0; i < 8; i++)
#pragma unroll
        for (int j = 0; j < 8; j++) acc[i][j] = 0.f;

    for (int k0 = 0; k0 < DM; k0 += 16) {
#pragma unroll
        for (int j = 0; j < 2; j++) {
            int i = tid + j * 256;          // 0..511 over 128 rows x 4 float4
            int r = i >> 2, c4 = (i & 3) * 4;
            float4 xv = *(const float4*)&X[(size_t)(m0 + r) * DM + k0 + c4];
            XsT[c4 + 0][r] = xv.x; XsT[c4 + 1][r] = xv.y;
            XsT[c4 + 2][r] = xv.z; XsT[c4 + 3][r] = xv.w;
            float4 wv = *(const float4*)&W[(size_t)(o0 + r) * DM + k0 + c4];
            WsT[c4 + 0][r] = wv.x; WsT[c4 + 1][r] = wv.y;
            WsT[c4 + 2][r] = wv.z; WsT[c4 + 3][r] = wv.w;
        }
        __syncthreads();
#pragma unroll
        for (int kk = 0; kk < 16; kk++) {
            float4 a0 = *(const float4*)&XsT[kk][ty * 4];
            float4 a1 = *(const float4*)&XsT[kk][64 + ty * 4];
            float4 bv0 = *(const float4*)&WsT[kk][tx * 4];
            float4 bv1 = *(const float4*)&WsT[kk][64 + tx * 4];
            float a[8] = {a0.x, a0.y, a0.z, a0.w, a1.x, a1.y, a1.z, a1.w};
            float b[8] = {bv0.x, bv0.y, bv0.z, bv0.w, bv1.x, bv1.y, bv1.z, bv1.w};
#pragma unroll
            for (int i = 0; i < 8; i++)
#pragma unroll
                for (int j = 0; j < 8; j++) acc[i][j] += a[i] * b[j];
        }
        __syncthreads();
    }

    const float sc = (mode == 0 && which == 0) ? SCALEF : 1.f;
#pragma unroll
    for (int i = 0; i < 8; i++) {
        int m = m0 + ((i < 4) ? ty * 4 + i : 64 + ty * 4 + (i - 4));
#pragma unroll
        for (int jg = 0; jg < 2; jg++) {
            int oc = o0 + ((jg == 0) ? tx * 4 : 64 + tx * 4);
            float4 v;
            v.x = (acc[i][jg * 4 + 0] + bias[oc + 0]) * sc;
            v.y = (acc[i][jg * 4 + 1] + bias[oc + 1]) * sc;
            v.z = (acc[i][jg * 4 + 2] + bias[oc + 2]) * sc;
            v.w = (acc[i][jg * 4 + 3] + bias[oc + 3]) * sc;
            if (mode == 0) {
                int b = m >> 11, n = m & (NN - 1);
                int h = oc >> 6, d = oc & 63;
                float* dst = (which == 0) ? g_Qh : (which == 1) ? g_Kh : g_Vh;
                *(float4*)&dst[(size_t)((b * NH + h) * NN + n) * HD + d] = v;
            } else {
                *(float4*)&outp[(size_t)m * DM + oc] = v;
            }
        }
    }
}

// ---------------------------------------------------------------------------
// Scores: per (b,h), S = Qh(2048x64) @ Kh^T. Q pre-scaled. 128x128 tiles,
// 8x8 micro-tile, K-dim (=64) staged in 2x BK=32 chunks. grid (16,16,16).
// ---------------------------------------------------------------------------
__global__ __launch_bounds__(256)
void scores_kernel()
{
    __shared__ float QsT[32][132];
    __shared__ float KsT[32][132];

    const int bh = blockIdx.z;
    const int kx = blockIdx.x * 128;
    const int qy = blockIdx.y * 128;
    const int tid = threadIdx.x;
    const int tx = tid & 15, ty = tid >> 4;

    float acc[8][8];
#pragma unroll
    for (int i = 0; i < 8; i++)
#pragma unroll
        for (int j = 0; j < 8; j++) acc[i][j] = 0.f;

    for (int kb = 0; kb < HD; kb += 32) {
#pragma unroll
        for (int j = 0; j < 4; j++) {
            int i = tid + j * 256;          // 0..1023 over 128 rows x 8 float4
            int r = i >> 3, c4 = (i & 7) * 4;
            float4 qv = *(const float4*)&g_Qh[((size_t)bh * NN + qy + r) * HD + kb + c4];
            QsT[c4 + 0][r] = qv.x; QsT[c4 + 1][r] = qv.y;
            QsT[c4 + 2][r] = qv.z; QsT[c4 + 3][r] = qv.w;
            float4 kv = *(const float4*)&g_Kh[((size_t)bh * NN + kx + r) * HD + kb + c4];
            KsT[c4 + 0][r] = kv.x; KsT[c4 + 1][r] = kv.y;
            KsT[c4 + 2][r] = kv.z; KsT[c4 + 3][r] = kv.w;
        }
        __syncthreads();
#pragma unroll
        for (int kk = 0; kk < 32; kk++) {
            float4 a0 = *(const float4*)&QsT[kk][ty * 4];
            float4 a1 = *(const float4*)&QsT[kk][64 + ty * 4];
            float4 bv0 = *(const float4*)&KsT[kk][tx * 4];
            float4 bv1 = *(const float4*)&KsT[kk][64 + tx * 4];
            float a[8] = {a0.x, a0.y, a0.z, a0.w, a1.x, a1.y, a1.z, a1.w};
            float b[8] = {bv0.x, bv0.y, bv0.z, bv0.w, bv1.x, bv1.y, bv1.z, bv1.w};
#pragma unroll
            for (int i = 0; i < 8; i++)
#pragma unroll
                for (int j = 0; j < 8; j++) acc[i][j] += a[i] * b[j];
        }
        __syncthreads();
    }

#pragma unroll
    for (int i = 0; i < 8; i++) {
        int row = qy + ((i < 4) ? ty * 4 + i : 64 + ty * 4 + (i - 4));
#pragma unroll
        for (int jg = 0; jg < 2; jg++) {
            int col = kx + ((jg == 0) ? tx * 4 : 64 + tx * 4);
            float4 v = make_float4(acc[i][jg * 4 + 0], acc[i][jg * 4 + 1],
                                   acc[i][jg * 4 + 2], acc[i][jg * 4 + 3]);
            __stcs((float4*)&g_S[((size_t)bh * NN + row) * NN + col], v);
        }
    }
}

// ---------------------------------------------------------------------------
// Per-row: exact top-64 (MSB radix select), softmax, attn row write, AV.
// Warp-shuffle scans/reductions, __expf, streaming loads.
// grid 32768 x 256.
// ---------------------------------------------------------------------------
__global__ __launch_bounds__(256)
void topk_av(float* __restrict__ attn, int write_attn)
{
    const int row = blockIdx.x;           // bh*N + q
    const int bh  = row >> 11;
    const int q   = row & (NN - 1);
    const int tid = threadIdx.x;
    const int lane = tid & 31, wid = tid >> 5;

    __shared__ int hist[256];
    __shared__ int wsum[8];
    __shared__ int wsuf[8];
    __shared__ float red[8];
    __shared__ int   sidx[128];
    __shared__ float sw[128];
    __shared__ unsigned sh_prefix;
    __shared__ int sh_kk;
    __shared__ int sh_cnt;
    __shared__ float sh_rmax, sh_invz;

    // load 8 scores per thread (coalesced: element e -> col e*256 + tid)
    float sreg[8];
    unsigned keys[8];
#pragma unroll
    for (int e = 0; e < 8; e++) {
        float f = __ldcs(&g_S[(size_t)row * NN + e * 256 + tid]);
        sreg[e] = f;
        unsigned u = __float_as_uint(f);
        keys[e] = (u & 0x80000000u) ? ~u : (u | 0x80000000u);
    }

    // ---- radix select: exact 64th-largest key, 4 x 8-bit MSB passes ----
    unsigned prefix = 0;
    int kk = TOPK;
    for (int pass = 0; pass < 4; pass++) {
        hist[tid] = 0;
        __syncthreads();
        int shift = 24 - 8 * pass;
#pragma unroll
        for (int e = 0; e < 8; e++) {
            unsigned k = keys[e];
            unsigned hi = (k >> (31 - 8 * pass)) >> 1;   // top 8*pass bits
            if (hi == prefix) atomicAdd(&hist[(k >> shift) & 255u], 1);
        }
        __syncthreads();
        int v = hist[tid];
        int s = v;                          // inclusive suffix sum within warp
#pragma unroll
        for (int off = 1; off < 32; off <<= 1) {
            int t = __shfl_down_sync(0xffffffffu, s, off);
            if (lane + off < 32) s += t;
        }
        if (lane == 0) wsum[wid] = s;       // warp total
        __syncthreads();
        if (tid < 8) {
            int t = 0;
            for (int j = tid + 1; j < 8; j++) t += wsum[j];
            wsuf[tid] = t;
        }
        __syncthreads();
        int S = s + wsuf[wid];              // count of elems with bin >= tid
        if (S >= kk && S - v < kk && v > 0) {
            sh_prefix = (prefix << 8) | (unsigned)tid;
            sh_kk = kk - (S - v);
        }
        __syncthreads();
        prefix = sh_prefix;
        kk = sh_kk;
        __syncthreads();
    }
    const unsigned kth = prefix;            // exact 64th-largest key

    // ---- row max (shuffle + cross-warp) ----
    float lmax = -3.4e38f;
#pragma unroll
    for (int e = 0; e < 8; e++) lmax = fmaxf(lmax, sreg[e]);
#pragma unroll
    for (int off = 16; off > 0; off >>= 1)
        lmax = fmaxf(lmax, __shfl_xor_sync(0xffffffffu, lmax, off));
    if (lane == 0) red[wid] = lmax;
    __syncthreads();
    if (tid == 0) {
        float m = red[0];
        for (int j = 1; j < 8; j++) m = fmaxf(m, red[j]);
        sh_rmax = m;
        sh_cnt = 0;
    }
    __syncthreads();
    const float rmax = sh_rmax;

    // ---- sum of exp over selected ----
    float lsum = 0.f;
#pragma unroll
    for (int e = 0; e < 8; e++)
        if (keys[e] >= kth) lsum += __expf(sreg[e] - rmax);
#pragma unroll
    for (int off = 16; off > 0; off >>= 1)
        lsum += __shfl_xor_sync(0xffffffffu, lsum, off);
    if (lane == 0) red[wid] = lsum;
    __syncthreads();
    if (tid == 0) {
        float z = 0.f;
        for (int j = 0; j < 8; j++) z += red[j];
        sh_invz = 1.f / z;
    }
    __syncthreads();
    const float inv_z = sh_invz;

    // ---- weights: write attn row, gather selected (idx, w) ----
#pragma unroll
    for (int e = 0; e < 8; e++) {
        bool sel = (keys[e] >= kth);
        float w = sel ? __expf(sreg[e] - rmax) * inv_z : 0.f;
        if (write_attn) __stcs(&attn[(size_t)row * NN + e * 256 + tid], w);
        if (sel) {
            int p = atomicAdd(&sh_cnt, 1);
            if (p < 128) { sidx[p] = e * 256 + tid; sw[p] = w; }
        }
    }
    __syncthreads();
    int cnt = sh_cnt; if (cnt > 128) cnt = 128;

    // ---- AV: out[d] = sum_j w_j * V[bh][idx_j][d] ----
    __shared__ float pacc[256];
    const int d = tid & 63;
    const int part = tid >> 6;
    float acc = 0.f;
    for (int j = part; j < cnt; j += 4)
        acc += sw[j] * g_Vh[(size_t)(bh * NN + sidx[j]) * HD + d];
    pacc[tid] = acc;
    __syncthreads();
    if (tid < 64) {
        float o = pacc[tid] + pacc[64 + tid] + pacc[128 + tid] + pacc[192 + tid];
        int b = bh >> 3, h = bh & 7;
        g_H[(size_t)(b * NN + q) * DM + h * HD + tid] = o;
    }
}

// ---------------------------------------------------------------------------
extern "C" void kernel_launch(void* const* d_in, const int* in_sizes, int n_in,
                              void* d_out, int out_size)
{
    const float* q  = (const float*)d_in[0];
    const float* k  = (const float*)d_in[1];
    const float* v  = (const float*)d_in[2];
    const float* wq = (const float*)d_in[3];
    const float* bq = (const float*)d_in[4];
    const float* wk = (const float*)d_in[5];
    const float* bk = (const float*)d_in[6];
    const float* wv = (const float*)d_in[7];
    const float* bv = (const float*)d_in[8];
    const float* wo = (const float*)d_in[9];
    const float* bo = (const float*)d_in[10];

    float* out = (float*)d_out;
    const long long OUT_ELEMS  = (long long)M_TOT * DM;        // 2,097,152
    const long long ATTN_ELEMS = (long long)BH * NN * NN;      // 67,108,864

    int write_attn = 0, write_out = 1;
    float* attn_ptr = nullptr;
    if ((long long)out_size >= OUT_ELEMS + ATTN_ELEMS) {
        write_attn = 1; attn_ptr = out + OUT_ELEMS;
    } else if ((long long)out_size == ATTN_ELEMS) {
        write_attn = 1; attn_ptr = out; write_out = 0;
    }

    // fused QKV projections: grid (12, 32)
    gemm128<<<dim3(12, M_TOT / 128), 256>>>(q, k, v, wq, wk, wv, bq, bk, bv,
                                            nullptr, 0);

    scores_kernel<<<dim3(NN / 128, NN / 128, BH), 256>>>();

    topk_av<<<BH * NN, 256>>>(attn_ptr, write_attn);

    if (write_out)
        gemm128<<<dim3(DM / 128, M_TOT / 128), 256>>>(nullptr, nullptr, nullptr,
                                                      wo, nullptr, nullptr,
                                                      bo, nullptr, nullptr,
                                                      out, 1);
}